// round 1
// baseline (speedup 1.0000x reference)
#include <cuda_runtime.h>
#include <math.h>

#define NB 2
#define NS 2048
#define ND 1024
#define NH 16
#define NE 64           // head dim
#define QTILE 64
#define PAD 68          // smem row pad (floats): 68*4=272 bytes, 16B aligned rows
#define SM_SCALE 0.125f // 1/sqrt(64)
#define NEG_BIG (-1e30f)

// Scratch for projected Q/K/V, layout [b*H+h][s][e] contiguous.
__device__ float g_q[(size_t)NB * NH * NS * NE];
__device__ float g_k[(size_t)NB * NH * NS * NE];
__device__ float g_v[(size_t)NB * NH * NS * NE];

// ---------------------------------------------------------------------------
// Projection kernel: out[b,h,s,e] = sum_d x[b,s,d] * W[h,d,e]
// One block = 64 s-rows x 64 e-cols for one (b,h,which). 256 threads, 4x4/thr.
// ---------------------------------------------------------------------------
__global__ __launch_bounds__(256) void proj_kernel(
    const float* __restrict__ x,
    const float* __restrict__ Wq,
    const float* __restrict__ Wk,
    const float* __restrict__ Wv)
{
    const int mt    = blockIdx.x;       // s tile
    const int bh    = blockIdx.y;       // b*H + h
    const int which = blockIdx.z;       // 0=q 1=k 2=v
    const int b = bh / NH;
    const int h = bh % NH;

    const float* W   = (which == 0) ? Wq : (which == 1) ? Wk : Wv;
    float*       dst = (which == 0) ? g_q : (which == 1) ? g_k : g_v;

    __shared__ float Xs[64][17];   // [m][kk], padded
    __shared__ float Ws[16][64];   // [kk][n]

    const int tid = threadIdx.x;
    const int ty  = tid >> 4;      // 0..15
    const int tx  = tid & 15;      // 0..15

    const float* xb = x + ((size_t)b * NS + (size_t)mt * 64) * ND;
    const float* Wh = W + (size_t)h * ND * NE;

    float acc[4][4] = {};

    for (int k0 = 0; k0 < ND; k0 += 16) {
        // Load X tile 64x16 (coalesced 16-float rows, conflict-free stores)
        {
            const int m0 = tid >> 4;     // 0..15
            const int kk = tid & 15;
            #pragma unroll
            for (int i = 0; i < 4; i++)
                Xs[m0 + i * 16][kk] = xb[(size_t)(m0 + i * 16) * ND + k0 + kk];
        }
        // Load W tile 16x64 (coalesced 64-float rows)
        {
            const int kk0 = tid >> 6;    // 0..3
            const int n   = tid & 63;
            #pragma unroll
            for (int i = 0; i < 4; i++)
                Ws[kk0 + i * 4][n] = Wh[(size_t)(k0 + kk0 + i * 4) * NE + n];
        }
        __syncthreads();

        #pragma unroll
        for (int kk = 0; kk < 16; kk++) {
            const float a0 = Xs[ty * 4 + 0][kk];
            const float a1 = Xs[ty * 4 + 1][kk];
            const float a2 = Xs[ty * 4 + 2][kk];
            const float a3 = Xs[ty * 4 + 3][kk];
            const float4 bv = *(const float4*)&Ws[kk][tx * 4];
            acc[0][0] = fmaf(a0, bv.x, acc[0][0]); acc[0][1] = fmaf(a0, bv.y, acc[0][1]);
            acc[0][2] = fmaf(a0, bv.z, acc[0][2]); acc[0][3] = fmaf(a0, bv.w, acc[0][3]);
            acc[1][0] = fmaf(a1, bv.x, acc[1][0]); acc[1][1] = fmaf(a1, bv.y, acc[1][1]);
            acc[1][2] = fmaf(a1, bv.z, acc[1][2]); acc[1][3] = fmaf(a1, bv.w, acc[1][3]);
            acc[2][0] = fmaf(a2, bv.x, acc[2][0]); acc[2][1] = fmaf(a2, bv.y, acc[2][1]);
            acc[2][2] = fmaf(a2, bv.z, acc[2][2]); acc[2][3] = fmaf(a2, bv.w, acc[2][3]);
            acc[3][0] = fmaf(a3, bv.x, acc[3][0]); acc[3][1] = fmaf(a3, bv.y, acc[3][1]);
            acc[3][2] = fmaf(a3, bv.z, acc[3][2]); acc[3][3] = fmaf(a3, bv.w, acc[3][3]);
        }
        __syncthreads();
    }

    float* ob = dst + ((size_t)bh * NS + (size_t)mt * 64) * NE;
    #pragma unroll
    for (int i = 0; i < 4; i++) {
        float4 v = make_float4(acc[i][0], acc[i][1], acc[i][2], acc[i][3]);
        *(float4*)&ob[(size_t)(ty * 4 + i) * NE + tx * 4] = v;
    }
}

// ---------------------------------------------------------------------------
// Flash-attention kernel. One block = one (b,h) x one 64-row query tile.
// Online softmax over causal KV tiles. 256 threads, each owns a 4x4 patch.
// smem: Qt[e][r], Kt[e][c] (transposed), Vs[c][e], Ps[r][c]; all rows PAD=68.
// ---------------------------------------------------------------------------
__global__ __launch_bounds__(256) void attn_kernel(float* __restrict__ out)
{
    extern __shared__ float sm[];
    float* Qt = sm;                 // 64*PAD  [e][r], pre-scaled by SM_SCALE
    float* Kt = Qt + 64 * PAD;      // 64*PAD  [e][c]
    float* Vs = Kt + 64 * PAD;      // 64*PAD  [c][e]
    float* Ps = Vs + 64 * PAD;      // 64*PAD  [r][c]

    const int qt = blockIdx.x;      // query tile
    const int bh = blockIdx.y;
    const int b  = bh / NH;
    const int h  = bh % NH;

    const float* qb = g_q + ((size_t)bh * NS + (size_t)qt * 64) * NE;
    const float* kb = g_k + (size_t)bh * NS * NE;
    const float* vb = g_v + (size_t)bh * NS * NE;

    const int tid = threadIdx.x;
    const int ty  = tid >> 4;
    const int tx  = tid & 15;

    // Load Q transposed + pre-scaled
    #pragma unroll
    for (int i = 0; i < 16; i++) {
        const int idx = tid + i * 256;
        const int r = idx >> 6, e = idx & 63;
        Qt[e * PAD + r] = qb[idx] * SM_SCALE;
    }

    float o[4][4] = {};
    float m_i[4] = {NEG_BIG, NEG_BIG, NEG_BIG, NEG_BIG};
    float l_i[4] = {};

    for (int kt = 0; kt <= qt; kt++) {
        __syncthreads();  // previous PV done before overwriting Kt/Vs
        const float* kpt = kb + (size_t)kt * 64 * NE;
        const float* vpt = vb + (size_t)kt * 64 * NE;
        #pragma unroll
        for (int i = 0; i < 16; i++) {
            const int idx = tid + i * 256;
            const int r = idx >> 6, e = idx & 63;
            Kt[e * PAD + r] = kpt[idx];
            Vs[r * PAD + e] = vpt[idx];
        }
        __syncthreads();  // tiles (and Qt on first iter) visible

        // Scores: sc[i][j] = sum_e Qt[e][ty*4+i] * Kt[e][tx*4+j]
        float sc[4][4] = {};
        #pragma unroll 8
        for (int e = 0; e < 64; e++) {
            const float4 qv = *(const float4*)&Qt[e * PAD + ty * 4];
            const float4 kv = *(const float4*)&Kt[e * PAD + tx * 4];
            sc[0][0] = fmaf(qv.x, kv.x, sc[0][0]); sc[0][1] = fmaf(qv.x, kv.y, sc[0][1]);
            sc[0][2] = fmaf(qv.x, kv.z, sc[0][2]); sc[0][3] = fmaf(qv.x, kv.w, sc[0][3]);
            sc[1][0] = fmaf(qv.y, kv.x, sc[1][0]); sc[1][1] = fmaf(qv.y, kv.y, sc[1][1]);
            sc[1][2] = fmaf(qv.y, kv.z, sc[1][2]); sc[1][3] = fmaf(qv.y, kv.w, sc[1][3]);
            sc[2][0] = fmaf(qv.z, kv.x, sc[2][0]); sc[2][1] = fmaf(qv.z, kv.y, sc[2][1]);
            sc[2][2] = fmaf(qv.z, kv.z, sc[2][2]); sc[2][3] = fmaf(qv.z, kv.w, sc[2][3]);
            sc[3][0] = fmaf(qv.w, kv.x, sc[3][0]); sc[3][1] = fmaf(qv.w, kv.y, sc[3][1]);
            sc[3][2] = fmaf(qv.w, kv.z, sc[3][2]); sc[3][3] = fmaf(qv.w, kv.w, sc[3][3]);
        }

        // Causal mask on diagonal tile (local row/col compare is exact there)
        if (kt == qt) {
            #pragma unroll
            for (int i = 0; i < 4; i++)
                #pragma unroll
                for (int j = 0; j < 4; j++)
                    if (tx * 4 + j > ty * 4 + i) sc[i][j] = NEG_BIG;
        }

        // Online softmax per row (reduce across the 16 tx lanes via shfl)
        #pragma unroll
        for (int i = 0; i < 4; i++) {
            float mx = fmaxf(fmaxf(sc[i][0], sc[i][1]), fmaxf(sc[i][2], sc[i][3]));
            #pragma unroll
            for (int off = 1; off < 16; off <<= 1)
                mx = fmaxf(mx, __shfl_xor_sync(0xffffffffu, mx, off));
            const float m_new = fmaxf(m_i[i], mx);
            const float corr  = __expf(m_i[i] - m_new);
            float p0 = __expf(sc[i][0] - m_new);
            float p1 = __expf(sc[i][1] - m_new);
            float p2 = __expf(sc[i][2] - m_new);
            float p3 = __expf(sc[i][3] - m_new);
            float rs = p0 + p1 + p2 + p3;
            #pragma unroll
            for (int off = 1; off < 16; off <<= 1)
                rs += __shfl_xor_sync(0xffffffffu, rs, off);
            l_i[i] = l_i[i] * corr + rs;
            m_i[i] = m_new;
            o[i][0] *= corr; o[i][1] *= corr; o[i][2] *= corr; o[i][3] *= corr;
            *(float4*)&Ps[(ty * 4 + i) * PAD + tx * 4] = make_float4(p0, p1, p2, p3);
        }
        __syncthreads();  // Ps complete before PV

        // PV: o[i][j] += sum_c Ps[ty*4+i][c] * Vs[c][tx*4+j]
        #pragma unroll 8
        for (int c = 0; c < 64; c++) {
            const float4 vv = *(const float4*)&Vs[c * PAD + tx * 4];
            const float p0 = Ps[(ty * 4 + 0) * PAD + c];
            const float p1 = Ps[(ty * 4 + 1) * PAD + c];
            const float p2 = Ps[(ty * 4 + 2) * PAD + c];
            const float p3 = Ps[(ty * 4 + 3) * PAD + c];
            o[0][0] = fmaf(p0, vv.x, o[0][0]); o[0][1] = fmaf(p0, vv.y, o[0][1]);
            o[0][2] = fmaf(p0, vv.z, o[0][2]); o[0][3] = fmaf(p0, vv.w, o[0][3]);
            o[1][0] = fmaf(p1, vv.x, o[1][0]); o[1][1] = fmaf(p1, vv.y, o[1][1]);
            o[1][2] = fmaf(p1, vv.z, o[1][2]); o[1][3] = fmaf(p1, vv.w, o[1][3]);
            o[2][0] = fmaf(p2, vv.x, o[2][0]); o[2][1] = fmaf(p2, vv.y, o[2][1]);
            o[2][2] = fmaf(p2, vv.z, o[2][2]); o[2][3] = fmaf(p2, vv.w, o[2][3]);
            o[3][0] = fmaf(p3, vv.x, o[3][0]); o[3][1] = fmaf(p3, vv.y, o[3][1]);
            o[3][2] = fmaf(p3, vv.z, o[3][2]); o[3][3] = fmaf(p3, vv.w, o[3][3]);
        }
    }

    // Normalize and write: out[b, s, h*NE + e], heads concatenated on last dim
    #pragma unroll
    for (int i = 0; i < 4; i++) {
        const float inv = 1.0f / l_i[i];
        const int srow = qt * 64 + ty * 4 + i;
        float* orow = out + ((size_t)b * NS + srow) * (NH * NE) + h * NE + tx * 4;
        *(float4*)orow = make_float4(o[i][0] * inv, o[i][1] * inv,
                                     o[i][2] * inv, o[i][3] * inv);
    }
}

// ---------------------------------------------------------------------------
extern "C" void kernel_launch(void* const* d_in, const int* in_sizes, int n_in,
                              void* d_out, int out_size)
{
    (void)in_sizes; (void)n_in; (void)out_size;
    const float* x  = (const float*)d_in[0];
    const float* Wq = (const float*)d_in[1];
    const float* Wk = (const float*)d_in[2];
    const float* Wv = (const float*)d_in[3];
    float* out = (float*)d_out;

    // QKV projections: 32 s-tiles x 32 (b,h) x 3 matrices
    proj_kernel<<<dim3(NS / 64, NB * NH, 3), 256>>>(x, Wq, Wk, Wv);

    // Flash attention: 32 q-tiles x 32 (b,h). 4 smem tiles of 64*PAD floats.
    const int smem_bytes = 4 * 64 * PAD * (int)sizeof(float);  // 69632
    cudaFuncSetAttribute(attn_kernel,
                         cudaFuncAttributeMaxDynamicSharedMemorySize, smem_bytes);
    attn_kernel<<<dim3(NS / 64, NB * NH), 256, smem_bytes>>>(out);
}

// round 3
// speedup vs baseline: 5.7470x; 5.7470x over previous
#include <cuda_runtime.h>
#include <cuda_fp16.h>
#include <math.h>
#include <stdint.h>

#define NB 2
#define NS 2048
#define ND 1024
#define NH 16
#define NE 64
#define SM_SCALE 0.125f
#define NEG_BIG (-1e30f)

// ---------------- scratch ----------------
__device__ __half g_qh[(size_t)NB * NH * NS * NE];
__device__ __half g_kh[(size_t)NB * NH * NS * NE];
__device__ __half g_vh[(size_t)NB * NH * NS * NE];
__device__ __half g_xh[(size_t)NB * NS * ND];        // x fp16 [b][s][k]
__device__ __half g_wt[(size_t)3 * NH * NE * ND];    // W^T fp16 [which][h][e][k]

// ---------------- helpers ----------------
__device__ __forceinline__ uint32_t smem_u32(const void* p) {
    uint32_t a;
    asm("{ .reg .u64 t; cvta.to.shared.u64 t, %1; cvt.u32.u64 %0, t; }" : "=r"(a) : "l"(p));
    return a;
}
__device__ __forceinline__ void ldsm_x4(uint32_t& r0, uint32_t& r1, uint32_t& r2, uint32_t& r3, uint32_t a) {
    asm volatile("ldmatrix.sync.aligned.m8n8.x4.shared.b16 {%0,%1,%2,%3}, [%4];"
                 : "=r"(r0), "=r"(r1), "=r"(r2), "=r"(r3) : "r"(a));
}
__device__ __forceinline__ void ldsm_x2(uint32_t& r0, uint32_t& r1, uint32_t a) {
    asm volatile("ldmatrix.sync.aligned.m8n8.x2.shared.b16 {%0,%1}, [%2];"
                 : "=r"(r0), "=r"(r1) : "r"(a));
}
__device__ __forceinline__ void ldsm_x2t(uint32_t& r0, uint32_t& r1, uint32_t a) {
    asm volatile("ldmatrix.sync.aligned.m8n8.x2.trans.shared.b16 {%0,%1}, [%2];"
                 : "=r"(r0), "=r"(r1) : "r"(a));
}
__device__ __forceinline__ void mma16816(float* d, uint32_t a0, uint32_t a1, uint32_t a2, uint32_t a3,
                                         uint32_t b0, uint32_t b1) {
    asm volatile("mma.sync.aligned.m16n8k16.row.col.f32.f16.f16.f32 "
                 "{%0,%1,%2,%3}, {%4,%5,%6,%7}, {%8,%9}, {%0,%1,%2,%3};"
                 : "+f"(d[0]), "+f"(d[1]), "+f"(d[2]), "+f"(d[3])
                 : "r"(a0), "r"(a1), "r"(a2), "r"(a3), "r"(b0), "r"(b1));
}
__device__ __forceinline__ uint32_t pack_h2(float x, float y) {
    __half2 h = __floats2half2_rn(x, y);
    return *(uint32_t*)&h;
}

// ---------------- convert kernels ----------------
__global__ __launch_bounds__(256) void convert_x_kernel(const float* __restrict__ x)
{
    const size_t n4 = (size_t)NB * NS * ND / 4;
    const float4* x4 = (const float4*)x;
    __half2* dst = (__half2*)g_xh;
    for (size_t i = blockIdx.x * 256 + threadIdx.x; i < n4; i += (size_t)gridDim.x * 256) {
        float4 v = x4[i];
        dst[2 * i]     = __floats2half2_rn(v.x, v.y);
        dst[2 * i + 1] = __floats2half2_rn(v.z, v.w);
    }
}

__global__ __launch_bounds__(256) void convert_w_kernel(
    const float* __restrict__ Wq, const float* __restrict__ Wk, const float* __restrict__ Wv)
{
    __shared__ __half T[64][65];
    const int kb = blockIdx.x, h = blockIdx.y, which = blockIdx.z;
    const float* W = (which == 0) ? Wq : (which == 1) ? Wk : Wv;
    const int k0 = kb * 64;
    const int tid = threadIdx.x;
    #pragma unroll
    for (int j = 0; j < 16; j++) {
        const int idx = tid + j * 256;
        const int kl = idx >> 6, e = idx & 63;
        T[e][kl] = __float2half(W[((size_t)h * ND + k0 + kl) * NE + e]);
    }
    __syncthreads();
    #pragma unroll
    for (int j = 0; j < 16; j++) {
        const int idx = tid + j * 256;
        const int e = idx >> 6, kl = idx & 63;
        g_wt[((size_t)(which * NH + h) * NE + e) * ND + k0 + kl] = T[e][kl];
    }
}

// ---------------- projection GEMM (HMMA) ----------------
// Block: 128(M) x 64(N=e) tile of C = X[2048,1024] @ W_h[1024,64], per (which,b,h).
// 8 warps in 4x2 grid, warp tile 32x32. K chunks of 64.
__global__ __launch_bounds__(256) void proj_kernel()
{
    __shared__ __half As[128][72];   // X tile, row-major m x k
    __shared__ __half Bs[64][72];    // W^T rows [e][k] -> col-major k x n

    const int tid = threadIdx.x, lane = tid & 31, warp = tid >> 5;
    const int mt = blockIdx.x, h = blockIdx.y;
    const int which = blockIdx.z >> 1, b = blockIdx.z & 1;
    const int wm = warp >> 1, wn = warp & 1;

    const uint4* x4 = (const uint4*)g_xh;
    const uint4* w4 = (const uint4*)g_wt;
    const size_t xbase = ((size_t)b * NS + (size_t)mt * 128) * (ND / 8);
    const size_t wbase = (size_t)(which * NH + h) * NE * (ND / 8);

    float acc[2][4][4] = {};

    for (int c = 0; c < 16; ++c) {
        if (c) __syncthreads();
        #pragma unroll
        for (int j = 0; j < 4; ++j) {
            const int idx = tid + j * 256;
            const int r = idx >> 3, c8 = idx & 7;
            *(uint4*)&As[r][c8 * 8] = x4[xbase + (size_t)r * (ND / 8) + c * 8 + c8];
        }
        #pragma unroll
        for (int j = 0; j < 2; ++j) {
            const int idx = tid + j * 256;
            const int r = idx >> 3, c8 = idx & 7;
            *(uint4*)&Bs[r][c8 * 8] = w4[wbase + (size_t)r * (ND / 8) + c * 8 + c8];
        }
        __syncthreads();

        #pragma unroll
        for (int kk = 0; kk < 4; ++kk) {
            const int k0 = kk * 16;
            uint32_t a[2][4];
            #pragma unroll
            for (int mi = 0; mi < 2; ++mi) {
                const int row = wm * 32 + mi * 16 + (lane & 15);
                const int col = k0 + ((lane & 16) ? 8 : 0);
                ldsm_x4(a[mi][0], a[mi][1], a[mi][2], a[mi][3], smem_u32(&As[row][col]));
            }
            #pragma unroll
            for (int nj = 0; nj < 4; ++nj) {
                const int l = lane & 15;
                const int row = wn * 32 + nj * 8 + (l & 7);
                const int col = k0 + ((l & 8) ? 8 : 0);
                uint32_t b0, b1;
                ldsm_x2(b0, b1, smem_u32(&Bs[row][col]));
                mma16816(acc[0][nj], a[0][0], a[0][1], a[0][2], a[0][3], b0, b1);
                mma16816(acc[1][nj], a[1][0], a[1][1], a[1][2], a[1][3], b0, b1);
            }
        }
    }

    __half* dst = (which == 0) ? g_qh : (which == 1) ? g_kh : g_vh;
    const size_t obase = ((size_t)(b * NH + h) * NS + (size_t)mt * 128) * NE;
    #pragma unroll
    for (int mi = 0; mi < 2; ++mi)
        #pragma unroll
        for (int nj = 0; nj < 4; ++nj) {
            const int r0 = wm * 32 + mi * 16 + (lane >> 2);
            const int e  = wn * 32 + nj * 8 + 2 * (lane & 3);
            uint32_t p0 = pack_h2(acc[mi][nj][0], acc[mi][nj][1]);
            uint32_t p1 = pack_h2(acc[mi][nj][2], acc[mi][nj][3]);
            *(uint32_t*)&dst[obase + (size_t)r0 * NE + e]       = p0;
            *(uint32_t*)&dst[obase + (size_t)(r0 + 8) * NE + e] = p1;
        }
}

// ---------------- flash attention (HMMA) ----------------
// Block: one (b,h) x 64-row q tile. 4 warps; warp w owns rows 16w..16w+15.
__global__ __launch_bounds__(128) void attn_kernel(float* __restrict__ out)
{
    __shared__ __half Qs[64][72];
    __shared__ __half Ks[64][72];
    __shared__ __half Vs[64][72];

    const int tid = threadIdx.x, lane = tid & 31, w = tid >> 5;
    const int qt = blockIdx.x, bh = blockIdx.y;
    const int b = bh >> 4, h = bh & 15;

    const uint4* qg = (const uint4*)g_qh + ((size_t)bh * NS + (size_t)qt * 64) * (NE / 8);
    const uint4* kg = (const uint4*)g_kh + (size_t)bh * NS * (NE / 8);
    const uint4* vg = (const uint4*)g_vh + (size_t)bh * NS * (NE / 8);

    #pragma unroll
    for (int j = 0; j < 4; ++j) {
        const int idx = tid + j * 128;
        const int r = idx >> 3, c8 = idx & 7;
        *(uint4*)&Qs[r][c8 * 8] = qg[(size_t)r * 8 + c8];
    }
    __syncthreads();

    // Q fragments, register-resident for the whole KV loop
    uint32_t qa[4][4];
    #pragma unroll
    for (int ks = 0; ks < 4; ++ks) {
        const int row = w * 16 + (lane & 15);
        const int col = ks * 16 + ((lane & 16) ? 8 : 0);
        ldsm_x4(qa[ks][0], qa[ks][1], qa[ks][2], qa[ks][3], smem_u32(&Qs[row][col]));
    }

    float o[8][4] = {};
    float m0 = NEG_BIG, m1 = NEG_BIG, l0 = 0.f, l1 = 0.f;

    for (int kt = 0; kt <= qt; ++kt) {
        __syncthreads();
        #pragma unroll
        for (int j = 0; j < 4; ++j) {
            const int idx = tid + j * 128;
            const int r = idx >> 3, c8 = idx & 7;
            *(uint4*)&Ks[r][c8 * 8] = kg[(size_t)(kt * 64 + r) * 8 + c8];
            *(uint4*)&Vs[r][c8 * 8] = vg[(size_t)(kt * 64 + r) * 8 + c8];
        }
        __syncthreads();

        // S = Q @ K^T  (rows w*16..+16, cols 0..64)
        float s[8][4] = {};
        #pragma unroll
        for (int kk = 0; kk < 4; ++kk) {
            #pragma unroll
            for (int nj = 0; nj < 8; ++nj) {
                const int l = lane & 15;
                uint32_t b0, b1;
                ldsm_x2(b0, b1, smem_u32(&Ks[nj * 8 + (l & 7)][kk * 16 + ((l & 8) ? 8 : 0)]));
                mma16816(s[nj], qa[kk][0], qa[kk][1], qa[kk][2], qa[kk][3], b0, b1);
            }
        }
        #pragma unroll
        for (int nj = 0; nj < 8; ++nj) {
            s[nj][0] *= SM_SCALE; s[nj][1] *= SM_SCALE;
            s[nj][2] *= SM_SCALE; s[nj][3] *= SM_SCALE;
        }

        // causal mask (diagonal tile only; local row/col compare is exact there)
        if (kt == qt) {
            const int r0 = w * 16 + (lane >> 2);
            #pragma unroll
            for (int nj = 0; nj < 8; ++nj) {
                const int cb = nj * 8 + 2 * (lane & 3);
                if (cb     > r0)     s[nj][0] = NEG_BIG;
                if (cb + 1 > r0)     s[nj][1] = NEG_BIG;
                if (cb     > r0 + 8) s[nj][2] = NEG_BIG;
                if (cb + 1 > r0 + 8) s[nj][3] = NEG_BIG;
            }
        }

        // online softmax: two rows per thread (r0, r0+8); reduce across lane%4
        float mx0 = NEG_BIG, mx1 = NEG_BIG;
        #pragma unroll
        for (int nj = 0; nj < 8; ++nj) {
            mx0 = fmaxf(mx0, fmaxf(s[nj][0], s[nj][1]));
            mx1 = fmaxf(mx1, fmaxf(s[nj][2], s[nj][3]));
        }
        mx0 = fmaxf(mx0, __shfl_xor_sync(0xffffffffu, mx0, 1));
        mx0 = fmaxf(mx0, __shfl_xor_sync(0xffffffffu, mx0, 2));
        mx1 = fmaxf(mx1, __shfl_xor_sync(0xffffffffu, mx1, 1));
        mx1 = fmaxf(mx1, __shfl_xor_sync(0xffffffffu, mx1, 2));

        const float mn0 = fmaxf(m0, mx0), mn1 = fmaxf(m1, mx1);
        const float c0 = __expf(m0 - mn0), c1 = __expf(m1 - mn1);
        m0 = mn0; m1 = mn1;

        float rs0 = 0.f, rs1 = 0.f;
        #pragma unroll
        for (int nj = 0; nj < 8; ++nj) {
            s[nj][0] = __expf(s[nj][0] - mn0);
            s[nj][1] = __expf(s[nj][1] - mn0);
            s[nj][2] = __expf(s[nj][2] - mn1);
            s[nj][3] = __expf(s[nj][3] - mn1);
            rs0 += s[nj][0] + s[nj][1];
            rs1 += s[nj][2] + s[nj][3];
        }
        rs0 += __shfl_xor_sync(0xffffffffu, rs0, 1);
        rs0 += __shfl_xor_sync(0xffffffffu, rs0, 2);
        rs1 += __shfl_xor_sync(0xffffffffu, rs1, 1);
        rs1 += __shfl_xor_sync(0xffffffffu, rs1, 2);
        l0 = l0 * c0 + rs0;
        l1 = l1 * c1 + rs1;

        #pragma unroll
        for (int nj = 0; nj < 8; ++nj) {
            o[nj][0] *= c0; o[nj][1] *= c0;
            o[nj][2] *= c1; o[nj][3] *= c1;
        }

        // P (f32 C-fragments) -> fp16 A-fragments, in-register
        uint32_t pa[4][4];
        #pragma unroll
        for (int ks = 0; ks < 4; ++ks) {
            pa[ks][0] = pack_h2(s[2 * ks][0],     s[2 * ks][1]);
            pa[ks][1] = pack_h2(s[2 * ks][2],     s[2 * ks][3]);
            pa[ks][2] = pack_h2(s[2 * ks + 1][0], s[2 * ks + 1][1]);
            pa[ks][3] = pack_h2(s[2 * ks + 1][2], s[2 * ks + 1][3]);
        }

        // O += P @ V  (V via ldmatrix.trans)
        #pragma unroll
        for (int ks = 0; ks < 4; ++ks) {
            #pragma unroll
            for (int nj = 0; nj < 8; ++nj) {
                uint32_t b0, b1;
                ldsm_x2t(b0, b1, smem_u32(&Vs[ks * 16 + (lane & 15)][nj * 8]));
                mma16816(o[nj], pa[ks][0], pa[ks][1], pa[ks][2], pa[ks][3], b0, b1);
            }
        }
    }

    // normalize + write out[b, s, h*64 + e]
    const float inv0 = 1.f / l0, inv1 = 1.f / l1;
    const int r0 = qt * 64 + w * 16 + (lane >> 2);
    #pragma unroll
    for (int nj = 0; nj < 8; ++nj) {
        const int e = nj * 8 + 2 * (lane & 3);
        float2 v0 = make_float2(o[nj][0] * inv0, o[nj][1] * inv0);
        float2 v1 = make_float2(o[nj][2] * inv1, o[nj][3] * inv1);
        *(float2*)&out[((size_t)b * NS + r0)     * (NH * NE) + h * NE + e] = v0;
        *(float2*)&out[((size_t)b * NS + r0 + 8) * (NH * NE) + h * NE + e] = v1;
    }
}

// ---------------------------------------------------------------------------
extern "C" void kernel_launch(void* const* d_in, const int* in_sizes, int n_in,
                              void* d_out, int out_size)
{
    (void)in_sizes; (void)n_in; (void)out_size;
    const float* x  = (const float*)d_in[0];
    const float* Wq = (const float*)d_in[1];
    const float* Wk = (const float*)d_in[2];
    const float* Wv = (const float*)d_in[3];
    float* out = (float*)d_out;

    convert_x_kernel<<<1024, 256>>>(x);
    convert_w_kernel<<<dim3(16, 16, 3), 256>>>(Wq, Wk, Wv);

    proj_kernel<<<dim3(16, 16, 6), 256>>>();

    attn_kernel<<<dim3(NS / 64, NB * NH), 128>>>(out);
}

// round 5
// speedup vs baseline: 7.2486x; 1.2613x over previous
#include <cuda_runtime.h>
#include <cuda_fp16.h>
#include <math.h>
#include <stdint.h>

#define NB 2
#define NS 2048
#define ND 1024
#define NH 16
#define NE 64
#define NEG_BIG (-1e30f)

// ---------------- scratch ----------------
__device__ __half g_qh[(size_t)NB * NH * NS * NE];   // pre-scaled by 0.125
__device__ __half g_kh[(size_t)NB * NH * NS * NE];
__device__ __half g_vh[(size_t)NB * NH * NS * NE];
__device__ __half g_xh[(size_t)NB * NS * ND];        // x fp16 [b][s][k]
__device__ __half g_wt[(size_t)3 * NH * NE * ND];    // W^T fp16 [which][h][e][k]

// ---------------- helpers ----------------
__device__ __forceinline__ uint32_t smem_u32(const void* p) {
    uint32_t a;
    asm("{ .reg .u64 t; cvta.to.shared.u64 t, %1; cvt.u32.u64 %0, t; }" : "=r"(a) : "l"(p));
    return a;
}
__device__ __forceinline__ void ldsm_x4(uint32_t& r0, uint32_t& r1, uint32_t& r2, uint32_t& r3, uint32_t a) {
    asm volatile("ldmatrix.sync.aligned.m8n8.x4.shared.b16 {%0,%1,%2,%3}, [%4];"
                 : "=r"(r0), "=r"(r1), "=r"(r2), "=r"(r3) : "r"(a));
}
__device__ __forceinline__ void ldsm_x4t(uint32_t& r0, uint32_t& r1, uint32_t& r2, uint32_t& r3, uint32_t a) {
    asm volatile("ldmatrix.sync.aligned.m8n8.x4.trans.shared.b16 {%0,%1,%2,%3}, [%4];"
                 : "=r"(r0), "=r"(r1), "=r"(r2), "=r"(r3) : "r"(a));
}
__device__ __forceinline__ void mma16816(float* d, const uint32_t* a, uint32_t b0, uint32_t b1) {
    asm volatile("mma.sync.aligned.m16n8k16.row.col.f32.f16.f16.f32 "
                 "{%0,%1,%2,%3}, {%4,%5,%6,%7}, {%8,%9}, {%0,%1,%2,%3};"
                 : "+f"(d[0]), "+f"(d[1]), "+f"(d[2]), "+f"(d[3])
                 : "r"(a[0]), "r"(a[1]), "r"(a[2]), "r"(a[3]), "r"(b0), "r"(b1));
}
__device__ __forceinline__ uint32_t pack_h2(float x, float y) {
    __half2 h = __floats2half2_rn(x, y);
    return *(uint32_t*)&h;
}
__device__ __forceinline__ void cp16(uint32_t dst, const void* src) {
    asm volatile("cp.async.cg.shared.global [%0], [%1], 16;" :: "r"(dst), "l"(src) : "memory");
}
#define CP_COMMIT() asm volatile("cp.async.commit_group;" ::: "memory")
#define CP_WAIT(N)  asm volatile("cp.async.wait_group %0;" :: "n"(N) : "memory")

// smem row stride: 72 halves = 144 bytes
#define RS 144

// ---------------- convert kernels ----------------
__global__ __launch_bounds__(256) void convert_x_kernel(const float* __restrict__ x)
{
    const size_t n4 = (size_t)NB * NS * ND / 4;
    const float4* x4 = (const float4*)x;
    __half2* dst = (__half2*)g_xh;
    for (size_t i = blockIdx.x * 256 + threadIdx.x; i < n4; i += (size_t)gridDim.x * 256) {
        float4 v = x4[i];
        dst[2 * i]     = __floats2half2_rn(v.x, v.y);
        dst[2 * i + 1] = __floats2half2_rn(v.z, v.w);
    }
}

__global__ __launch_bounds__(256) void convert_w_kernel(
    const float* __restrict__ Wq, const float* __restrict__ Wk, const float* __restrict__ Wv)
{
    __shared__ __half T[64][65];
    const int kb = blockIdx.x, h = blockIdx.y, which = blockIdx.z;
    const float* W = (which == 0) ? Wq : (which == 1) ? Wk : Wv;
    const int k0 = kb * 64;
    const int tid = threadIdx.x;
    #pragma unroll
    for (int j = 0; j < 16; j++) {
        const int idx = tid + j * 256;
        const int kl = idx >> 6, e = idx & 63;
        T[e][kl] = __float2half(W[((size_t)h * ND + k0 + kl) * NE + e]);
    }
    __syncthreads();
    #pragma unroll
    for (int j = 0; j < 16; j++) {
        const int idx = tid + j * 256;
        const int e = idx >> 6, kl = idx & 63;
        g_wt[((size_t)(which * NH + h) * NE + e) * ND + k0 + kl] = T[e][kl];
    }
}

// ---------------- projection GEMM (HMMA, 128x128 per block, 2 heads) -------
// smem: buf{0,1} x (A 128x72h = 18432B, B 128x72h = 18432B) = 73728B
#define P_ABUF(buf) ((buf) * 36864u)
#define P_BBUF(buf) ((buf) * 36864u + 18432u)

__device__ __forceinline__ void proj_load(uint32_t sb, int buf,
                                          const uint4* x4, const uint4* w4,
                                          size_t xbase, size_t wbase, int c, int tid)
{
    const uint32_t ab = sb + P_ABUF(buf), bb = sb + P_BBUF(buf);
    #pragma unroll
    for (int j = 0; j < 4; ++j) {
        const int idx = tid + j * 256;
        const int r = idx >> 3, c8 = idx & 7;
        const uint32_t doff = (uint32_t)(r * RS + c8 * 16);
        cp16(ab + doff, x4 + xbase + (size_t)r * (ND / 8) + c * 8 + c8);
        cp16(bb + doff, w4 + wbase + (size_t)r * (ND / 8) + c * 8 + c8);
    }
}

__global__ __launch_bounds__(256, 2) void proj_kernel()
{
    extern __shared__ char psm[];
    const uint32_t sb = smem_u32(psm);
    const int tid = threadIdx.x, lane = tid & 31, warp = tid >> 5;
    const int mt = blockIdx.x;                 // 16 m-tiles of 128
    const int h0 = blockIdx.y * 2;             // head pair
    const int which = blockIdx.z >> 1, b = blockIdx.z & 1;
    const int wm = warp >> 1, wn = warp & 1;   // 4x2 warp grid, tile 32x64

    const uint4* x4 = (const uint4*)g_xh;
    const uint4* w4 = (const uint4*)g_wt;
    const size_t xbase = ((size_t)b * NS + (size_t)mt * 128) * (ND / 8);
    const size_t wbase = (size_t)(which * NH + h0) * NE * (ND / 8);

    float acc[2][8][4] = {};
    const int g = lane >> 3;

    proj_load(sb, 0, x4, w4, xbase, wbase, 0, tid);
    CP_COMMIT();

    for (int c = 0; c < 16; ++c) {
        const int buf = c & 1;
        if (c + 1 < 16) {
            proj_load(sb, buf ^ 1, x4, w4, xbase, wbase, c + 1, tid);
            CP_COMMIT();
            CP_WAIT(1);
        } else {
            CP_WAIT(0);
        }
        __syncthreads();

        const uint32_t ab = sb + P_ABUF(buf), bb = sb + P_BBUF(buf);
        const uint32_t a_addr = ab + (uint32_t)((wm * 32 + (lane & 15)) * RS + (lane >> 4) * 16);
        const uint32_t b_addr = bb + (uint32_t)(((g >> 1) * 8 + (lane & 7)) * RS + (g & 1) * 16
                                                + wn * 64 * RS);
        #pragma unroll
        for (int kk = 0; kk < 4; ++kk) {
            uint32_t a[2][4];
            ldsm_x4(a[0][0], a[0][1], a[0][2], a[0][3], a_addr + kk * 32);
            ldsm_x4(a[1][0], a[1][1], a[1][2], a[1][3], a_addr + kk * 32 + 16 * RS);
            #pragma unroll
            for (int njp = 0; njp < 4; ++njp) {
                uint32_t b0, b1, b2, b3;
                ldsm_x4(b0, b1, b2, b3, b_addr + njp * 16 * RS + kk * 32);
                mma16816(acc[0][2 * njp],     a[0], b0, b1);
                mma16816(acc[0][2 * njp + 1], a[0], b2, b3);
                mma16816(acc[1][2 * njp],     a[1], b0, b1);
                mma16816(acc[1][2 * njp + 1], a[1], b2, b3);
            }
        }
        __syncthreads();
    }

    // epilogue: fold softmax scale into Q
    const float scl = (which == 0) ? 0.125f : 1.0f;
    __half* dst = (which == 0) ? g_qh : (which == 1) ? g_kh : g_vh;
    const int h = h0 + wn;
    const size_t obase = ((size_t)(b * NH + h) * NS + (size_t)mt * 128) * NE;
    #pragma unroll
    for (int mi = 0; mi < 2; ++mi)
        #pragma unroll
        for (int nj = 0; nj < 8; ++nj) {
            const int r0 = wm * 32 + mi * 16 + (lane >> 2);
            const int e  = nj * 8 + 2 * (lane & 3);
            uint32_t p0 = pack_h2(acc[mi][nj][0] * scl, acc[mi][nj][1] * scl);
            uint32_t p1 = pack_h2(acc[mi][nj][2] * scl, acc[mi][nj][3] * scl);
            *(uint32_t*)&dst[obase + (size_t)r0 * NE + e]       = p0;
            *(uint32_t*)&dst[obase + (size_t)(r0 + 8) * NE + e] = p1;
        }
}

// ---------------- flash attention (HMMA, cp.async double buffer) -----------
// smem: Q 9216B, then buf{0,1} x (K 9216B, V 9216B) = 46080B total
#define A_KBUF(buf) (9216u + (buf) * 18432u)
#define A_VBUF(buf) (9216u + (buf) * 18432u + 9216u)

__device__ __forceinline__ void attn_load_kv(uint32_t sb, int buf,
                                             const uint4* kg, const uint4* vg,
                                             int kt, int tid)
{
    const uint32_t kb_s = sb + A_KBUF(buf), vb_s = sb + A_VBUF(buf);
    #pragma unroll
    for (int j = 0; j < 4; ++j) {
        const int idx = tid + j * 128;
        const int r = idx >> 3, c8 = idx & 7;
        const uint32_t doff = (uint32_t)(r * RS + c8 * 16);
        cp16(kb_s + doff, kg + (size_t)(kt * 64 + r) * 8 + c8);
        cp16(vb_s + doff, vg + (size_t)(kt * 64 + r) * 8 + c8);
    }
}

__global__ __launch_bounds__(128, 3) void attn_kernel(float* __restrict__ out)
{
    extern __shared__ char asm_[];
    const uint32_t sb = smem_u32(asm_);
    __half* Qs = (__half*)asm_;

    const int tid = threadIdx.x, lane = tid & 31, w = tid >> 5;
    const int qt = blockIdx.x, bh = blockIdx.y;
    const int b = bh >> 4, h = bh & 15;
    const int g = lane >> 3;

    const uint4* qg = (const uint4*)g_qh + ((size_t)bh * NS + (size_t)qt * 64) * (NE / 8);
    const uint4* kg = (const uint4*)g_kh + (size_t)bh * NS * (NE / 8);
    const uint4* vg = (const uint4*)g_vh + (size_t)bh * NS * (NE / 8);

    // load Q (already scaled) + prefetch KV tile 0
    #pragma unroll
    for (int j = 0; j < 4; ++j) {
        const int idx = tid + j * 128;
        const int r = idx >> 3, c8 = idx & 7;
        *(uint4*)((char*)Qs + r * RS + c8 * 16) = qg[(size_t)r * 8 + c8];
    }
    attn_load_kv(sb, 0, kg, vg, 0, tid);
    CP_COMMIT();
    __syncthreads();

    uint32_t qa[4][4];
    {
        const uint32_t q_addr = sb + (uint32_t)((w * 16 + (lane & 15)) * RS + (lane >> 4) * 16);
        #pragma unroll
        for (int kk = 0; kk < 4; ++kk)
            ldsm_x4(qa[kk][0], qa[kk][1], qa[kk][2], qa[kk][3], q_addr + kk * 32);
    }

    float o[8][4] = {};
    float m0 = NEG_BIG, m1 = NEG_BIG, l0 = 0.f, l1 = 0.f;

    for (int kt = 0; kt <= qt; ++kt) {
        const int buf = kt & 1;
        if (kt < qt) {
            attn_load_kv(sb, buf ^ 1, kg, vg, kt + 1, tid);
            CP_COMMIT();
            CP_WAIT(1);
        } else {
            CP_WAIT(0);
        }
        __syncthreads();

        // S = Q @ K^T
        float s[8][4] = {};
        {
            const uint32_t kaddr = sb + A_KBUF(buf)
                + (uint32_t)(((g >> 1) * 8 + (lane & 7)) * RS + (g & 1) * 16);
            #pragma unroll
            for (int kk = 0; kk < 4; ++kk)
                #pragma unroll
                for (int njp = 0; njp < 4; ++njp) {
                    uint32_t b0, b1, b2, b3;
                    ldsm_x4(b0, b1, b2, b3, kaddr + njp * 16 * RS + kk * 32);
                    mma16816(s[2 * njp],     qa[kk], b0, b1);
                    mma16816(s[2 * njp + 1], qa[kk], b2, b3);
                }
        }

        // causal mask on diagonal tile
        if (kt == qt) {
            const int r0 = w * 16 + (lane >> 2);
            #pragma unroll
            for (int nj = 0; nj < 8; ++nj) {
                const int cb = nj * 8 + 2 * (lane & 3);
                if (cb     > r0)     s[nj][0] = NEG_BIG;
                if (cb + 1 > r0)     s[nj][1] = NEG_BIG;
                if (cb     > r0 + 8) s[nj][2] = NEG_BIG;
                if (cb + 1 > r0 + 8) s[nj][3] = NEG_BIG;
            }
        }

        // online softmax, rows r0 and r0+8
        float mx0 = NEG_BIG, mx1 = NEG_BIG;
        #pragma unroll
        for (int nj = 0; nj < 8; ++nj) {
            mx0 = fmaxf(mx0, fmaxf(s[nj][0], s[nj][1]));
            mx1 = fmaxf(mx1, fmaxf(s[nj][2], s[nj][3]));
        }
        mx0 = fmaxf(mx0, __shfl_xor_sync(0xffffffffu, mx0, 1));
        mx0 = fmaxf(mx0, __shfl_xor_sync(0xffffffffu, mx0, 2));
        mx1 = fmaxf(mx1, __shfl_xor_sync(0xffffffffu, mx1, 1));
        mx1 = fmaxf(mx1, __shfl_xor_sync(0xffffffffu, mx1, 2));

        const float mn0 = fmaxf(m0, mx0), mn1 = fmaxf(m1, mx1);
        const float c0 = __expf(m0 - mn0), c1 = __expf(m1 - mn1);
        m0 = mn0; m1 = mn1;

        float rs0 = 0.f, rs1 = 0.f;
        #pragma unroll
        for (int nj = 0; nj < 8; ++nj) {
            s[nj][0] = __expf(s[nj][0] - mn0);
            s[nj][1] = __expf(s[nj][1] - mn0);
            s[nj][2] = __expf(s[nj][2] - mn1);
            s[nj][3] = __expf(s[nj][3] - mn1);
            rs0 += s[nj][0] + s[nj][1];
            rs1 += s[nj][2] + s[nj][3];
        }
        rs0 += __shfl_xor_sync(0xffffffffu, rs0, 1);
        rs0 += __shfl_xor_sync(0xffffffffu, rs0, 2);
        rs1 += __shfl_xor_sync(0xffffffffu, rs1, 1);
        rs1 += __shfl_xor_sync(0xffffffffu, rs1, 2);
        l0 = l0 * c0 + rs0;
        l1 = l1 * c1 + rs1;

        #pragma unroll
        for (int nj = 0; nj < 8; ++nj) {
            o[nj][0] *= c0; o[nj][1] *= c0;
            o[nj][2] *= c1; o[nj][3] *= c1;
        }

        // P fp32 -> fp16 A fragments (in-register)
        uint32_t pa[4][4];
        #pragma unroll
        for (int ks = 0; ks < 4; ++ks) {
            pa[ks][0] = pack_h2(s[2 * ks][0],     s[2 * ks][1]);
            pa[ks][1] = pack_h2(s[2 * ks][2],     s[2 * ks][3]);
            pa[ks][2] = pack_h2(s[2 * ks + 1][0], s[2 * ks + 1][1]);
            pa[ks][3] = pack_h2(s[2 * ks + 1][2], s[2 * ks + 1][3]);
        }

        // O += P @ V
        {
            const uint32_t vaddr = sb + A_VBUF(buf)
                + (uint32_t)(((g & 1) * 8 + (lane & 7)) * RS + (g >> 1) * 16);
            #pragma unroll
            for (int ks = 0; ks < 4; ++ks)
                #pragma unroll
                for (int njp = 0; njp < 4; ++njp) {
                    uint32_t b0, b1, b2, b3;
                    ldsm_x4t(b0, b1, b2, b3, vaddr + ks * 16 * RS + njp * 32);
                    mma16816(o[2 * njp],     pa[ks], b0, b1);
                    mma16816(o[2 * njp + 1], pa[ks], b2, b3);
                }
        }
        __syncthreads();
    }

    // normalize + write out[b, s, h*64 + e]
    const float inv0 = 1.f / l0, inv1 = 1.f / l1;
    const int r0 = qt * 64 + w * 16 + (lane >> 2);
    #pragma unroll
    for (int nj = 0; nj < 8; ++nj) {
        const int e = nj * 8 + 2 * (lane & 3);
        float2 v0 = make_float2(o[nj][0] * inv0, o[nj][1] * inv0);
        float2 v1 = make_float2(o[nj][2] * inv1, o[nj][3] * inv1);
        *(float2*)&out[((size_t)b * NS + r0)     * (NH * NE) + h * NE + e] = v0;
        *(float2*)&out[((size_t)b * NS + r0 + 8) * (NH * NE) + h * NE + e] = v1;
    }
}

// ---------------------------------------------------------------------------
extern "C" void kernel_launch(void* const* d_in, const int* in_sizes, int n_in,
                              void* d_out, int out_size)
{
    (void)in_sizes; (void)n_in; (void)out_size;
    const float* x  = (const float*)d_in[0];
    const float* Wq = (const float*)d_in[1];
    const float* Wk = (const float*)d_in[2];
    const float* Wv = (const float*)d_in[3];
    float* out = (float*)d_out;

    convert_x_kernel<<<1024, 256>>>(x);
    convert_w_kernel<<<dim3(16, 16, 3), 256>>>(Wq, Wk, Wv);

    cudaFuncSetAttribute(proj_kernel,
                         cudaFuncAttributeMaxDynamicSharedMemorySize, 73728);
    proj_kernel<<<dim3(16, 8, 6), 256, 73728>>>();

    cudaFuncSetAttribute(attn_kernel,
                         cudaFuncAttributeMaxDynamicSharedMemorySize, 46080);
    attn_kernel<<<dim3(NS / 64, NB * NH), 128, 46080>>>(out);
}

// round 6
// speedup vs baseline: 7.3404x; 1.0127x over previous
#include <cuda_runtime.h>
#include <cuda_fp16.h>
#include <math.h>
#include <stdint.h>

#define NB 2
#define NS 2048
#define ND 1024
#define NH 16
#define NE 64
#define NEG_BIG (-1e30f)

// ---------------- scratch ----------------
__device__ __half g_qh[(size_t)NB * NH * NS * NE];   // pre-scaled by 0.125
__device__ __half g_kh[(size_t)NB * NH * NS * NE];
__device__ __half g_vh[(size_t)NB * NH * NS * NE];
__device__ __half g_xh[(size_t)NB * NS * ND];        // x fp16 [b][s][k]
__device__ __half g_wt[(size_t)3 * NH * NE * ND];    // W^T fp16 [which][h][e][k]

// ---------------- helpers ----------------
__device__ __forceinline__ uint32_t smem_u32(const void* p) {
    uint32_t a;
    asm("{ .reg .u64 t; cvta.to.shared.u64 t, %1; cvt.u32.u64 %0, t; }" : "=r"(a) : "l"(p));
    return a;
}
__device__ __forceinline__ void ldsm_x4(uint32_t& r0, uint32_t& r1, uint32_t& r2, uint32_t& r3, uint32_t a) {
    asm volatile("ldmatrix.sync.aligned.m8n8.x4.shared.b16 {%0,%1,%2,%3}, [%4];"
                 : "=r"(r0), "=r"(r1), "=r"(r2), "=r"(r3) : "r"(a));
}
__device__ __forceinline__ void ldsm_x4t(uint32_t& r0, uint32_t& r1, uint32_t& r2, uint32_t& r3, uint32_t a) {
    asm volatile("ldmatrix.sync.aligned.m8n8.x4.trans.shared.b16 {%0,%1,%2,%3}, [%4];"
                 : "=r"(r0), "=r"(r1), "=r"(r2), "=r"(r3) : "r"(a));
}
__device__ __forceinline__ void mma16816(float* d, const uint32_t* a, uint32_t b0, uint32_t b1) {
    asm volatile("mma.sync.aligned.m16n8k16.row.col.f32.f16.f16.f32 "
                 "{%0,%1,%2,%3}, {%4,%5,%6,%7}, {%8,%9}, {%0,%1,%2,%3};"
                 : "+f"(d[0]), "+f"(d[1]), "+f"(d[2]), "+f"(d[3])
                 : "r"(a[0]), "r"(a[1]), "r"(a[2]), "r"(a[3]), "r"(b0), "r"(b1));
}
__device__ __forceinline__ uint32_t pack_h2(float x, float y) {
    __half2 h = __floats2half2_rn(x, y);
    return *(uint32_t*)&h;
}
__device__ __forceinline__ void cp16(uint32_t dst, const void* src) {
    asm volatile("cp.async.cg.shared.global [%0], [%1], 16;" :: "r"(dst), "l"(src) : "memory");
}
#define CP_COMMIT() asm volatile("cp.async.commit_group;" ::: "memory")
#define CP_WAIT(N)  asm volatile("cp.async.wait_group %0;" :: "n"(N) : "memory")

// smem row stride: 72 halves = 144 bytes
#define RS 144

// ---------------- convert kernels ----------------
__global__ __launch_bounds__(256) void convert_x_kernel(const float* __restrict__ x)
{
    const size_t n4 = (size_t)NB * NS * ND / 4;
    const float4* x4 = (const float4*)x;
    __half2* dst = (__half2*)g_xh;
    for (size_t i = blockIdx.x * 256 + threadIdx.x; i < n4; i += (size_t)gridDim.x * 256) {
        float4 v = x4[i];
        dst[2 * i]     = __floats2half2_rn(v.x, v.y);
        dst[2 * i + 1] = __floats2half2_rn(v.z, v.w);
    }
}

__global__ __launch_bounds__(256) void convert_w_kernel(
    const float* __restrict__ Wq, const float* __restrict__ Wk, const float* __restrict__ Wv)
{
    __shared__ __half T[64][65];
    const int kb = blockIdx.x, h = blockIdx.y, which = blockIdx.z;
    const float* W = (which == 0) ? Wq : (which == 1) ? Wk : Wv;
    const int k0 = kb * 64;
    const int tid = threadIdx.x;
    #pragma unroll
    for (int j = 0; j < 16; j++) {
        const int idx = tid + j * 256;
        const int kl = idx >> 6, e = idx & 63;
        T[e][kl] = __float2half(W[((size_t)h * ND + k0 + kl) * NE + e]);
    }
    __syncthreads();
    #pragma unroll
    for (int j = 0; j < 16; j++) {
        const int idx = tid + j * 256;
        const int e = idx >> 6, kl = idx & 63;
        g_wt[((size_t)(which * NH + h) * NE + e) * ND + k0 + kl] = T[e][kl];
    }
}

// ---------------- projection GEMM (HMMA, 128x128 per block, 2 heads) -------
#define P_ABUF(buf) ((buf) * 36864u)
#define P_BBUF(buf) ((buf) * 36864u + 18432u)

__device__ __forceinline__ void proj_load(uint32_t sb, int buf,
                                          const uint4* x4, const uint4* w4,
                                          size_t xbase, size_t wbase, int c, int tid)
{
    const uint32_t ab = sb + P_ABUF(buf), bb = sb + P_BBUF(buf);
    #pragma unroll
    for (int j = 0; j < 4; ++j) {
        const int idx = tid + j * 256;
        const int r = idx >> 3, c8 = idx & 7;
        const uint32_t doff = (uint32_t)(r * RS + c8 * 16);
        cp16(ab + doff, x4 + xbase + (size_t)r * (ND / 8) + c * 8 + c8);
        cp16(bb + doff, w4 + wbase + (size_t)r * (ND / 8) + c * 8 + c8);
    }
}

__global__ __launch_bounds__(256, 2) void proj_kernel()
{
    extern __shared__ char psm[];
    const uint32_t sb = smem_u32(psm);
    const int tid = threadIdx.x, lane = tid & 31, warp = tid >> 5;
    const int mt = blockIdx.x;
    const int h0 = blockIdx.y * 2;
    const int which = blockIdx.z >> 1, b = blockIdx.z & 1;
    const int wm = warp >> 1, wn = warp & 1;

    const uint4* x4 = (const uint4*)g_xh;
    const uint4* w4 = (const uint4*)g_wt;
    const size_t xbase = ((size_t)b * NS + (size_t)mt * 128) * (ND / 8);
    const size_t wbase = (size_t)(which * NH + h0) * NE * (ND / 8);

    float acc[2][8][4] = {};
    const int g = lane >> 3;

    proj_load(sb, 0, x4, w4, xbase, wbase, 0, tid);
    CP_COMMIT();

    for (int c = 0; c < 16; ++c) {
        const int buf = c & 1;
        if (c + 1 < 16) {
            proj_load(sb, buf ^ 1, x4, w4, xbase, wbase, c + 1, tid);
            CP_COMMIT();
            CP_WAIT(1);
        } else {
            CP_WAIT(0);
        }
        __syncthreads();

        const uint32_t ab = sb + P_ABUF(buf), bb = sb + P_BBUF(buf);
        const uint32_t a_addr = ab + (uint32_t)((wm * 32 + (lane & 15)) * RS + (lane >> 4) * 16);
        const uint32_t b_addr = bb + (uint32_t)(((g >> 1) * 8 + (lane & 7)) * RS + (g & 1) * 16
                                                + wn * 64 * RS);
        #pragma unroll
        for (int kk = 0; kk < 4; ++kk) {
            uint32_t a[2][4];
            ldsm_x4(a[0][0], a[0][1], a[0][2], a[0][3], a_addr + kk * 32);
            ldsm_x4(a[1][0], a[1][1], a[1][2], a[1][3], a_addr + kk * 32 + 16 * RS);
            #pragma unroll
            for (int njp = 0; njp < 4; ++njp) {
                uint32_t b0, b1, b2, b3;
                ldsm_x4(b0, b1, b2, b3, b_addr + njp * 16 * RS + kk * 32);
                mma16816(acc[0][2 * njp],     a[0], b0, b1);
                mma16816(acc[0][2 * njp + 1], a[0], b2, b3);
                mma16816(acc[1][2 * njp],     a[1], b0, b1);
                mma16816(acc[1][2 * njp + 1], a[1], b2, b3);
            }
        }
        __syncthreads();
    }

    const float scl = (which == 0) ? 0.125f : 1.0f;
    __half* dst = (which == 0) ? g_qh : (which == 1) ? g_kh : g_vh;
    const int h = h0 + wn;
    const size_t obase = ((size_t)(b * NH + h) * NS + (size_t)mt * 128) * NE;
    #pragma unroll
    for (int mi = 0; mi < 2; ++mi)
        #pragma unroll
        for (int nj = 0; nj < 8; ++nj) {
            const int r0 = wm * 32 + mi * 16 + (lane >> 2);
            const int e  = nj * 8 + 2 * (lane & 3);
            uint32_t p0 = pack_h2(acc[mi][nj][0] * scl, acc[mi][nj][1] * scl);
            uint32_t p1 = pack_h2(acc[mi][nj][2] * scl, acc[mi][nj][3] * scl);
            *(uint32_t*)&dst[obase + (size_t)r0 * NE + e]       = p0;
            *(uint32_t*)&dst[obase + (size_t)(r0 + 8) * NE + e] = p1;
        }
}

// ---------------- flash attention (HMMA, balanced q-tile pairs) ------------
// Block x = 0..15 processes q-tiles {x, 31-x}: uniform 33 KV tiles per block.
// smem: Q 9216B, then buf{0,1} x (K 9216B, V 9216B) = 46080B total
#define A_KBUF(buf) (9216u + (buf) * 18432u)
#define A_VBUF(buf) (9216u + (buf) * 18432u + 9216u)

__device__ __forceinline__ void attn_load_kv(uint32_t sb, int buf,
                                             const uint4* kg, const uint4* vg,
                                             int kt, int tid)
{
    const uint32_t kb_s = sb + A_KBUF(buf), vb_s = sb + A_VBUF(buf);
    #pragma unroll
    for (int j = 0; j < 4; ++j) {
        const int idx = tid + j * 128;
        const int r = idx >> 3, c8 = idx & 7;
        const uint32_t doff = (uint32_t)(r * RS + c8 * 16);
        cp16(kb_s + doff, kg + (size_t)(kt * 64 + r) * 8 + c8);
        cp16(vb_s + doff, vg + (size_t)(kt * 64 + r) * 8 + c8);
    }
}

__global__ __launch_bounds__(128, 3) void attn_kernel(float* __restrict__ out)
{
    extern __shared__ char asm_[];
    const uint32_t sb = smem_u32(asm_);
    __half* Qs = (__half*)asm_;

    const int tid = threadIdx.x, lane = tid & 31, w = tid >> 5;
    const int bh = blockIdx.y;
    const int b = bh >> 4, h = bh & 15;
    const int g = lane >> 3;

    const uint4* kg = (const uint4*)g_kh + (size_t)bh * NS * (NE / 8);
    const uint4* vg = (const uint4*)g_vh + (size_t)bh * NS * (NE / 8);

    #pragma unroll
    for (int pass = 0; pass < 2; ++pass) {
        const int qt = pass ? (31 - (int)blockIdx.x) : (int)blockIdx.x;
        const uint4* qg = (const uint4*)g_qh + ((size_t)bh * NS + (size_t)qt * 64) * (NE / 8);

        // load Q (already scaled) + prefetch KV tile 0
        #pragma unroll
        for (int j = 0; j < 4; ++j) {
            const int idx = tid + j * 128;
            const int r = idx >> 3, c8 = idx & 7;
            *(uint4*)((char*)Qs + r * RS + c8 * 16) = qg[(size_t)r * 8 + c8];
        }
        attn_load_kv(sb, 0, kg, vg, 0, tid);
        CP_COMMIT();
        __syncthreads();

        uint32_t qa[4][4];
        {
            const uint32_t q_addr = sb + (uint32_t)((w * 16 + (lane & 15)) * RS + (lane >> 4) * 16);
            #pragma unroll
            for (int kk = 0; kk < 4; ++kk)
                ldsm_x4(qa[kk][0], qa[kk][1], qa[kk][2], qa[kk][3], q_addr + kk * 32);
        }

        float o[8][4] = {};
        float m0 = NEG_BIG, m1 = NEG_BIG, l0 = 0.f, l1 = 0.f;

        for (int kt = 0; kt <= qt; ++kt) {
            const int buf = kt & 1;
            if (kt < qt) {
                attn_load_kv(sb, buf ^ 1, kg, vg, kt + 1, tid);
                CP_COMMIT();
                CP_WAIT(1);
            } else {
                CP_WAIT(0);
            }
            __syncthreads();

            // S = Q @ K^T
            float s[8][4] = {};
            {
                const uint32_t kaddr = sb + A_KBUF(buf)
                    + (uint32_t)(((g >> 1) * 8 + (lane & 7)) * RS + (g & 1) * 16);
                #pragma unroll
                for (int kk = 0; kk < 4; ++kk)
                    #pragma unroll
                    for (int njp = 0; njp < 4; ++njp) {
                        uint32_t b0, b1, b2, b3;
                        ldsm_x4(b0, b1, b2, b3, kaddr + njp * 16 * RS + kk * 32);
                        mma16816(s[2 * njp],     qa[kk], b0, b1);
                        mma16816(s[2 * njp + 1], qa[kk], b2, b3);
                    }
            }

            // causal mask on diagonal tile
            if (kt == qt) {
                const int r0 = w * 16 + (lane >> 2);
                #pragma unroll
                for (int nj = 0; nj < 8; ++nj) {
                    const int cb = nj * 8 + 2 * (lane & 3);
                    if (cb     > r0)     s[nj][0] = NEG_BIG;
                    if (cb + 1 > r0)     s[nj][1] = NEG_BIG;
                    if (cb     > r0 + 8) s[nj][2] = NEG_BIG;
                    if (cb + 1 > r0 + 8) s[nj][3] = NEG_BIG;
                }
            }

            // online softmax, rows r0 and r0+8
            float mx0 = NEG_BIG, mx1 = NEG_BIG;
            #pragma unroll
            for (int nj = 0; nj < 8; ++nj) {
                mx0 = fmaxf(mx0, fmaxf(s[nj][0], s[nj][1]));
                mx1 = fmaxf(mx1, fmaxf(s[nj][2], s[nj][3]));
            }
            mx0 = fmaxf(mx0, __shfl_xor_sync(0xffffffffu, mx0, 1));
            mx0 = fmaxf(mx0, __shfl_xor_sync(0xffffffffu, mx0, 2));
            mx1 = fmaxf(mx1, __shfl_xor_sync(0xffffffffu, mx1, 1));
            mx1 = fmaxf(mx1, __shfl_xor_sync(0xffffffffu, mx1, 2));

            const float mn0 = fmaxf(m0, mx0), mn1 = fmaxf(m1, mx1);
            const float c0 = __expf(m0 - mn0), c1 = __expf(m1 - mn1);
            m0 = mn0; m1 = mn1;

            float rs0 = 0.f, rs1 = 0.f;
            #pragma unroll
            for (int nj = 0; nj < 8; ++nj) {
                s[nj][0] = __expf(s[nj][0] - mn0);
                s[nj][1] = __expf(s[nj][1] - mn0);
                s[nj][2] = __expf(s[nj][2] - mn1);
                s[nj][3] = __expf(s[nj][3] - mn1);
                rs0 += s[nj][0] + s[nj][1];
                rs1 += s[nj][2] + s[nj][3];
            }
            rs0 += __shfl_xor_sync(0xffffffffu, rs0, 1);
            rs0 += __shfl_xor_sync(0xffffffffu, rs0, 2);
            rs1 += __shfl_xor_sync(0xffffffffu, rs1, 1);
            rs1 += __shfl_xor_sync(0xffffffffu, rs1, 2);
            l0 = l0 * c0 + rs0;
            l1 = l1 * c1 + rs1;

            #pragma unroll
            for (int nj = 0; nj < 8; ++nj) {
                o[nj][0] *= c0; o[nj][1] *= c0;
                o[nj][2] *= c1; o[nj][3] *= c1;
            }

            // P fp32 -> fp16 A fragments (in-register)
            uint32_t pa[4][4];
            #pragma unroll
            for (int ks = 0; ks < 4; ++ks) {
                pa[ks][0] = pack_h2(s[2 * ks][0],     s[2 * ks][1]);
                pa[ks][1] = pack_h2(s[2 * ks][2],     s[2 * ks][3]);
                pa[ks][2] = pack_h2(s[2 * ks + 1][0], s[2 * ks + 1][1]);
                pa[ks][3] = pack_h2(s[2 * ks + 1][2], s[2 * ks + 1][3]);
            }

            // O += P @ V
            {
                const uint32_t vaddr = sb + A_VBUF(buf)
                    + (uint32_t)(((g & 1) * 8 + (lane & 7)) * RS + (g >> 1) * 16);
                #pragma unroll
                for (int ks = 0; ks < 4; ++ks)
                    #pragma unroll
                    for (int njp = 0; njp < 4; ++njp) {
                        uint32_t b0, b1, b2, b3;
                        ldsm_x4t(b0, b1, b2, b3, vaddr + ks * 16 * RS + njp * 32);
                        mma16816(o[2 * njp],     pa[ks], b0, b1);
                        mma16816(o[2 * njp + 1], pa[ks], b2, b3);
                    }
            }
            __syncthreads();
        }

        // normalize + write out[b, s, h*64 + e]
        const float inv0 = 1.f / l0, inv1 = 1.f / l1;
        const int r0 = qt * 64 + w * 16 + (lane >> 2);
        #pragma unroll
        for (int nj = 0; nj < 8; ++nj) {
            const int e = nj * 8 + 2 * (lane & 3);
            float2 v0 = make_float2(o[nj][0] * inv0, o[nj][1] * inv0);
            float2 v1 = make_float2(o[nj][2] * inv1, o[nj][3] * inv1);
            *(float2*)&out[((size_t)b * NS + r0)     * (NH * NE) + h * NE + e] = v0;
            *(float2*)&out[((size_t)b * NS + r0 + 8) * (NH * NE) + h * NE + e] = v1;
        }
    }
}

// ---------------------------------------------------------------------------
extern "C" void kernel_launch(void* const* d_in, const int* in_sizes, int n_in,
                              void* d_out, int out_size)
{
    (void)in_sizes; (void)n_in; (void)out_size;
    const float* x  = (const float*)d_in[0];
    const float* Wq = (const float*)d_in[1];
    const float* Wk = (const float*)d_in[2];
    const float* Wv = (const float*)d_in[3];
    float* out = (float*)d_out;

    convert_x_kernel<<<1024, 256>>>(x);
    convert_w_kernel<<<dim3(16, 16, 3), 256>>>(Wq, Wk, Wv);

    cudaFuncSetAttribute(proj_kernel,
                         cudaFuncAttributeMaxDynamicSharedMemorySize, 73728);
    proj_kernel<<<dim3(16, 8, 6), 256, 73728>>>();

    cudaFuncSetAttribute(attn_kernel,
                         cudaFuncAttributeMaxDynamicSharedMemorySize, 46080);
    attn_kernel<<<dim3(16, NB * NH), 128, 46080>>>(out);
}

// round 8
// speedup vs baseline: 7.5269x; 1.0254x over previous
#include <cuda_runtime.h>
#include <cuda_fp16.h>
#include <math.h>
#include <stdint.h>

#define NB 2
#define NS 2048
#define ND 1024
#define NH 16
#define NE 64
#define NEG_BIG (-1e30f)
#define LOG2E 1.44269504088896f

// ---------------- scratch ----------------
__device__ __half g_qh[(size_t)NB * NH * NS * NE];   // pre-scaled by 0.125*log2(e)
__device__ __half g_kh[(size_t)NB * NH * NS * NE];
__device__ __half g_vh[(size_t)NB * NH * NS * NE];
__device__ __half g_xh[(size_t)NB * NS * ND];        // x fp16 [b][s][k]
__device__ __half g_wt[(size_t)3 * NH * NE * ND];    // W^T fp16 [which][h][e][k]

// ---------------- helpers ----------------
__device__ __forceinline__ uint32_t smem_u32(const void* p) {
    uint32_t a;
    asm("{ .reg .u64 t; cvta.to.shared.u64 t, %1; cvt.u32.u64 %0, t; }" : "=r"(a) : "l"(p));
    return a;
}
__device__ __forceinline__ void ldsm_x4(uint32_t& r0, uint32_t& r1, uint32_t& r2, uint32_t& r3, uint32_t a) {
    asm volatile("ldmatrix.sync.aligned.m8n8.x4.shared.b16 {%0,%1,%2,%3}, [%4];"
                 : "=r"(r0), "=r"(r1), "=r"(r2), "=r"(r3) : "r"(a));
}
__device__ __forceinline__ void ldsm_x4t(uint32_t& r0, uint32_t& r1, uint32_t& r2, uint32_t& r3, uint32_t a) {
    asm volatile("ldmatrix.sync.aligned.m8n8.x4.trans.shared.b16 {%0,%1,%2,%3}, [%4];"
                 : "=r"(r0), "=r"(r1), "=r"(r2), "=r"(r3) : "r"(a));
}
__device__ __forceinline__ void mma16816(float* d, const uint32_t* a, uint32_t b0, uint32_t b1) {
    asm volatile("mma.sync.aligned.m16n8k16.row.col.f32.f16.f16.f32 "
                 "{%0,%1,%2,%3}, {%4,%5,%6,%7}, {%8,%9}, {%0,%1,%2,%3};"
                 : "+f"(d[0]), "+f"(d[1]), "+f"(d[2]), "+f"(d[3])
                 : "r"(a[0]), "r"(a[1]), "r"(a[2]), "r"(a[3]), "r"(b0), "r"(b1));
}
__device__ __forceinline__ uint32_t pack_h2(float x, float y) {
    __half2 h = __floats2half2_rn(x, y);
    return *(uint32_t*)&h;
}
__device__ __forceinline__ void cp16(uint32_t dst, const void* src) {
    asm volatile("cp.async.cg.shared.global [%0], [%1], 16;" :: "r"(dst), "l"(src) : "memory");
}
#define CP_COMMIT() asm volatile("cp.async.commit_group;" ::: "memory")
#define CP_WAIT(N)  asm volatile("cp.async.wait_group %0;" :: "n"(N) : "memory")
__device__ __forceinline__ float ex2(float x) {
    float r;
    asm("ex2.approx.f32 %0, %1;" : "=f"(r) : "f"(x));
    return r;
}

// smem row stride: 72 halves = 144 bytes
#define RS 144

// ---------------- convert kernels ----------------
__global__ __launch_bounds__(256) void convert_x_kernel(const float* __restrict__ x)
{
    const size_t n4 = (size_t)NB * NS * ND / 4;
    const float4* x4 = (const float4*)x;
    __half2* dst = (__half2*)g_xh;
    for (size_t i = blockIdx.x * 256 + threadIdx.x; i < n4; i += (size_t)gridDim.x * 256) {
        float4 v = x4[i];
        dst[2 * i]     = __floats2half2_rn(v.x, v.y);
        dst[2 * i + 1] = __floats2half2_rn(v.z, v.w);
    }
}

__global__ __launch_bounds__(256) void convert_w_kernel(
    const float* __restrict__ Wq, const float* __restrict__ Wk, const float* __restrict__ Wv)
{
    __shared__ __half T[64][65];
    const int kb = blockIdx.x, h = blockIdx.y, which = blockIdx.z;
    const float* W = (which == 0) ? Wq : (which == 1) ? Wk : Wv;
    const int k0 = kb * 64;
    const int tid = threadIdx.x;
    #pragma unroll
    for (int j = 0; j < 16; j++) {
        const int idx = tid + j * 256;
        const int kl = idx >> 6, e = idx & 63;
        T[e][kl] = __float2half(W[((size_t)h * ND + k0 + kl) * NE + e]);
    }
    __syncthreads();
    #pragma unroll
    for (int j = 0; j < 16; j++) {
        const int idx = tid + j * 256;
        const int e = idx >> 6, kl = idx & 63;
        g_wt[((size_t)(which * NH + h) * NE + e) * ND + k0 + kl] = T[e][kl];
    }
}

// ---------------- projection GEMM (HMMA, 128x128 per block, 2 heads) -------
#define P_ABUF(buf) ((buf) * 36864u)
#define P_BBUF(buf) ((buf) * 36864u + 18432u)

__device__ __forceinline__ void proj_load(uint32_t sb, int buf,
                                          const uint4* x4, const uint4* w4,
                                          size_t xbase, size_t wbase, int c, int tid)
{
    const uint32_t ab = sb + P_ABUF(buf), bb = sb + P_BBUF(buf);
    #pragma unroll
    for (int j = 0; j < 4; ++j) {
        const int idx = tid + j * 256;
        const int r = idx >> 3, c8 = idx & 7;
        const uint32_t doff = (uint32_t)(r * RS + c8 * 16);
        cp16(ab + doff, x4 + xbase + (size_t)r * (ND / 8) + c * 8 + c8);
        cp16(bb + doff, w4 + wbase + (size_t)r * (ND / 8) + c * 8 + c8);
    }
}

__global__ __launch_bounds__(256, 2) void proj_kernel()
{
    extern __shared__ char psm[];
    const uint32_t sb = smem_u32(psm);
    const int tid = threadIdx.x, lane = tid & 31, warp = tid >> 5;
    const int mt = blockIdx.x;
    const int h0 = blockIdx.y * 2;
    const int which = blockIdx.z >> 1, b = blockIdx.z & 1;
    const int wm = warp >> 1, wn = warp & 1;

    const uint4* x4 = (const uint4*)g_xh;
    const uint4* w4 = (const uint4*)g_wt;
    const size_t xbase = ((size_t)b * NS + (size_t)mt * 128) * (ND / 8);
    const size_t wbase = (size_t)(which * NH + h0) * NE * (ND / 8);

    float acc[2][8][4] = {};
    const int g = lane >> 3;

    proj_load(sb, 0, x4, w4, xbase, wbase, 0, tid);
    CP_COMMIT();

    for (int c = 0; c < 16; ++c) {
        const int buf = c & 1;
        if (c + 1 < 16) {
            proj_load(sb, buf ^ 1, x4, w4, xbase, wbase, c + 1, tid);
            CP_COMMIT();
            CP_WAIT(1);
        } else {
            CP_WAIT(0);
        }
        __syncthreads();

        const uint32_t ab = sb + P_ABUF(buf), bb = sb + P_BBUF(buf);
        const uint32_t a_addr = ab + (uint32_t)((wm * 32 + (lane & 15)) * RS + (lane >> 4) * 16);
        const uint32_t b_addr = bb + (uint32_t)(((g >> 1) * 8 + (lane & 7)) * RS + (g & 1) * 16
                                                + wn * 64 * RS);
        #pragma unroll
        for (int kk = 0; kk < 4; ++kk) {
            uint32_t a[2][4];
            ldsm_x4(a[0][0], a[0][1], a[0][2], a[0][3], a_addr + kk * 32);
            ldsm_x4(a[1][0], a[1][1], a[1][2], a[1][3], a_addr + kk * 32 + 16 * RS);
            #pragma unroll
            for (int njp = 0; njp < 4; ++njp) {
                uint32_t b0, b1, b2, b3;
                ldsm_x4(b0, b1, b2, b3, b_addr + njp * 16 * RS + kk * 32);
                mma16816(acc[0][2 * njp],     a[0], b0, b1);
                mma16816(acc[0][2 * njp + 1], a[0], b2, b3);
                mma16816(acc[1][2 * njp],     a[1], b0, b1);
                mma16816(acc[1][2 * njp + 1], a[1], b2, b3);
            }
        }
        __syncthreads();
    }

    // epilogue: fold softmax scale AND log2(e) into Q (single fp32 mult + one
    // fp16 rounding either way — no extra precision loss vs plain 0.125)
    const float scl = (which == 0) ? 0.125f * LOG2E : 1.0f;
    __half* dst = (which == 0) ? g_qh : (which == 1) ? g_kh : g_vh;
    const int h = h0 + wn;
    const size_t obase = ((size_t)(b * NH + h) * NS + (size_t)mt * 128) * NE;
    #pragma unroll
    for (int mi = 0; mi < 2; ++mi)
        #pragma unroll
        for (int nj = 0; nj < 8; ++nj) {
            const int r0 = wm * 32 + mi * 16 + (lane >> 2);
            const int e  = nj * 8 + 2 * (lane & 3);
            uint32_t p0 = pack_h2(acc[mi][nj][0] * scl, acc[mi][nj][1] * scl);
            uint32_t p1 = pack_h2(acc[mi][nj][2] * scl, acc[mi][nj][3] * scl);
            *(uint32_t*)&dst[obase + (size_t)r0 * NE + e]       = p0;
            *(uint32_t*)&dst[obase + (size_t)(r0 + 8) * NE + e] = p1;
        }
}

// ---------------- flash attention (HMMA, 3-stage ring, exp2 softmax) -------
// Block x = 0..15 processes q-tiles {x, 31-x}: uniform 33 KV tiles per block.
// smem: Q 9216B, then ring buf{0,1,2} x (K 9216B, V 9216B) = 64512B total
#define A_KBUF(buf) (9216u + (buf) * 18432u)
#define A_VBUF(buf) (9216u + (buf) * 18432u + 9216u)

__device__ __forceinline__ void attn_load_kv(uint32_t sb, int buf,
                                             const uint4* kg, const uint4* vg,
                                             int kt, int tid)
{
    const uint32_t kb_s = sb + A_KBUF(buf), vb_s = sb + A_VBUF(buf);
    #pragma unroll
    for (int j = 0; j < 4; ++j) {
        const int idx = tid + j * 128;
        const int r = idx >> 3, c8 = idx & 7;
        const uint32_t doff = (uint32_t)(r * RS + c8 * 16);
        cp16(kb_s + doff, kg + (size_t)(kt * 64 + r) * 8 + c8);
        cp16(vb_s + doff, vg + (size_t)(kt * 64 + r) * 8 + c8);
    }
}

__global__ __launch_bounds__(128, 3) void attn_kernel(float* __restrict__ out)
{
    extern __shared__ char asm_[];
    const uint32_t sb = smem_u32(asm_);
    __half* Qs = (__half*)asm_;

    const int tid = threadIdx.x, lane = tid & 31, w = tid >> 5;
    const int bh = blockIdx.y;
    const int b = bh >> 4, h = bh & 15;
    const int g = lane >> 3;

    const uint4* kg = (const uint4*)g_kh + (size_t)bh * NS * (NE / 8);
    const uint4* vg = (const uint4*)g_vh + (size_t)bh * NS * (NE / 8);

    #pragma unroll
    for (int pass = 0; pass < 2; ++pass) {
        const int qt = pass ? (31 - (int)blockIdx.x) : (int)blockIdx.x;
        const uint4* qg = (const uint4*)g_qh + ((size_t)bh * NS + (size_t)qt * 64) * (NE / 8);

        // load Q (pre-scaled, log2 domain) + prefetch KV tile 0 into ring slot 0
        #pragma unroll
        for (int j = 0; j < 4; ++j) {
            const int idx = tid + j * 128;
            const int r = idx >> 3, c8 = idx & 7;
            *(uint4*)((char*)Qs + r * RS + c8 * 16) = qg[(size_t)r * 8 + c8];
        }
        attn_load_kv(sb, 0, kg, vg, 0, tid);
        CP_COMMIT();
        __syncthreads();

        uint32_t qa[4][4];
        {
            const uint32_t q_addr = sb + (uint32_t)((w * 16 + (lane & 15)) * RS + (lane >> 4) * 16);
            #pragma unroll
            for (int kk = 0; kk < 4; ++kk)
                ldsm_x4(qa[kk][0], qa[kk][1], qa[kk][2], qa[kk][3], q_addr + kk * 32);
        }

        float o[8][4] = {};
        float m0 = NEG_BIG, m1 = NEG_BIG, l0 = 0.f, l1 = 0.f;

        int buf = 0;
        for (int kt = 0; kt <= qt; ++kt) {
            if (kt < qt) {
                int nbuf = buf + 1; if (nbuf == 3) nbuf = 0;
                attn_load_kv(sb, nbuf, kg, vg, kt + 1, tid);
                CP_COMMIT();
                CP_WAIT(1);
            } else {
                CP_WAIT(0);
            }
            __syncthreads();   // sole sync per tile (3-deep ring makes trailing sync redundant)

            // S = Q @ K^T  (log2 domain)
            float s[8][4] = {};
            {
                const uint32_t kaddr = sb + A_KBUF(buf)
                    + (uint32_t)(((g >> 1) * 8 + (lane & 7)) * RS + (g & 1) * 16);
                #pragma unroll
                for (int kk = 0; kk < 4; ++kk)
                    #pragma unroll
                    for (int njp = 0; njp < 4; ++njp) {
                        uint32_t b0, b1, b2, b3;
                        ldsm_x4(b0, b1, b2, b3, kaddr + njp * 16 * RS + kk * 32);
                        mma16816(s[2 * njp],     qa[kk], b0, b1);
                        mma16816(s[2 * njp + 1], qa[kk], b2, b3);
                    }
            }

            // causal mask on diagonal tile
            if (kt == qt) {
                const int r0 = w * 16 + (lane >> 2);
                #pragma unroll
                for (int nj = 0; nj < 8; ++nj) {
                    const int cb = nj * 8 + 2 * (lane & 3);
                    if (cb     > r0)     s[nj][0] = NEG_BIG;
                    if (cb + 1 > r0)     s[nj][1] = NEG_BIG;
                    if (cb     > r0 + 8) s[nj][2] = NEG_BIG;
                    if (cb + 1 > r0 + 8) s[nj][3] = NEG_BIG;
                }
            }

            // online softmax in log2 domain, rows r0 and r0+8
            float mx0 = NEG_BIG, mx1 = NEG_BIG;
            #pragma unroll
            for (int nj = 0; nj < 8; ++nj) {
                mx0 = fmaxf(mx0, fmaxf(s[nj][0], s[nj][1]));
                mx1 = fmaxf(mx1, fmaxf(s[nj][2], s[nj][3]));
            }
            mx0 = fmaxf(mx0, __shfl_xor_sync(0xffffffffu, mx0, 1));
            mx0 = fmaxf(mx0, __shfl_xor_sync(0xffffffffu, mx0, 2));
            mx1 = fmaxf(mx1, __shfl_xor_sync(0xffffffffu, mx1, 1));
            mx1 = fmaxf(mx1, __shfl_xor_sync(0xffffffffu, mx1, 2));

            const float mn0 = fmaxf(m0, mx0), mn1 = fmaxf(m1, mx1);
            const float c0 = ex2(m0 - mn0), c1 = ex2(m1 - mn1);
            m0 = mn0; m1 = mn1;

            float rs0 = 0.f, rs1 = 0.f;
            #pragma unroll
            for (int nj = 0; nj < 8; ++nj) {
                s[nj][0] = ex2(s[nj][0] - mn0);
                s[nj][1] = ex2(s[nj][1] - mn0);
                s[nj][2] = ex2(s[nj][2] - mn1);
                s[nj][3] = ex2(s[nj][3] - mn1);
                rs0 += s[nj][0] + s[nj][1];
                rs1 += s[nj][2] + s[nj][3];
            }
            rs0 += __shfl_xor_sync(0xffffffffu, rs0, 1);
            rs0 += __shfl_xor_sync(0xffffffffu, rs0, 2);
            rs1 += __shfl_xor_sync(0xffffffffu, rs1, 1);
            rs1 += __shfl_xor_sync(0xffffffffu, rs1, 2);
            l0 = l0 * c0 + rs0;
            l1 = l1 * c1 + rs1;

            #pragma unroll
            for (int nj = 0; nj < 8; ++nj) {
                o[nj][0] *= c0; o[nj][1] *= c0;
                o[nj][2] *= c1; o[nj][3] *= c1;
            }

            // P fp32 -> fp16 A fragments (in-register)
            uint32_t pa[4][4];
            #pragma unroll
            for (int ks = 0; ks < 4; ++ks) {
                pa[ks][0] = pack_h2(s[2 * ks][0],     s[2 * ks][1]);
                pa[ks][1] = pack_h2(s[2 * ks][2],     s[2 * ks][3]);
                pa[ks][2] = pack_h2(s[2 * ks + 1][0], s[2 * ks + 1][1]);
                pa[ks][3] = pack_h2(s[2 * ks + 1][2], s[2 * ks + 1][3]);
            }

            // O += P @ V
            {
                const uint32_t vaddr = sb + A_VBUF(buf)
                    + (uint32_t)(((g & 1) * 8 + (lane & 7)) * RS + (g >> 1) * 16);
                #pragma unroll
                for (int ks = 0; ks < 4; ++ks)
                    #pragma unroll
                    for (int njp = 0; njp < 4; ++njp) {
                        uint32_t b0, b1, b2, b3;
                        ldsm_x4t(b0, b1, b2, b3, vaddr + ks * 16 * RS + njp * 32);
                        mma16816(o[2 * njp],     pa[ks], b0, b1);
                        mma16816(o[2 * njp + 1], pa[ks], b2, b3);
                    }
            }
            if (++buf == 3) buf = 0;
        }

        // normalize + write out[b, s, h*64 + e]
        const float inv0 = 1.f / l0, inv1 = 1.f / l1;
        const int r0 = qt * 64 + w * 16 + (lane >> 2);
        #pragma unroll
        for (int nj = 0; nj < 8; ++nj) {
            const int e = nj * 8 + 2 * (lane & 3);
            float2 v0 = make_float2(o[nj][0] * inv0, o[nj][1] * inv0);
            float2 v1 = make_float2(o[nj][2] * inv1, o[nj][3] * inv1);
            *(float2*)&out[((size_t)b * NS + r0)     * (NH * NE) + h * NE + e] = v0;
            *(float2*)&out[((size_t)b * NS + r0 + 8) * (NH * NE) + h * NE + e] = v1;
        }
        __syncthreads();  // protect ring slot 0 before next pass overwrites it
    }
}

// ---------------------------------------------------------------------------
extern "C" void kernel_launch(void* const* d_in, const int* in_sizes, int n_in,
                              void* d_out, int out_size)
{
    (void)in_sizes; (void)n_in; (void)out_size;
    const float* x  = (const float*)d_in[0];
    const float* Wq = (const float*)d_in[1];
    const float* Wk = (const float*)d_in[2];
    const float* Wv = (const float*)d_in[3];
    float* out = (float*)d_out;

    convert_x_kernel<<<1024, 256>>>(x);
    convert_w_kernel<<<dim3(16, 16, 3), 256>>>(Wq, Wk, Wv);

    cudaFuncSetAttribute(proj_kernel,
                         cudaFuncAttributeMaxDynamicSharedMemorySize, 73728);
    proj_kernel<<<dim3(16, 8, 6), 256, 73728>>>();

    cudaFuncSetAttribute(attn_kernel,
                         cudaFuncAttributeMaxDynamicSharedMemorySize, 64512);
    attn_kernel<<<dim3(16, NB * NH), 128, 64512>>>(out);
}